// round 4
// baseline (speedup 1.0000x reference)
#include <cuda_runtime.h>

// Problem constants (fixed by the dataset)
#define NQ      10880          // total queries = BATCH * tok_per_img
#define TOKB    5440           // valid tokens per image (4096+1024+256+64)
#define EMB     256
#define NHEADS  8
#define HD      32
#define NLEV    4
#define NPTS    4

// Scratch (device globals — no allocation allowed)
__device__ float g_values[2 * TOKB * EMB];      // compact projected values  [b][tok][h*32+d]
__device__ float g_offattw[NQ * 384];           // per-query: 256 offsets | 128 attn logits
__device__ float g_attn_out[NQ * EMB];          // per-query sampled+weighted output

__constant__ int c_loff[4] = {0, 4096, 5120, 5376};

// ---------------------------------------------------------------------------
// Generic fp32 GEMM: C[m, col0+n] = sum_k A[m,k] * B[k,n] + bias[n]
// K = 256 fixed.  M multiple of 64 (grid.x = M/64), N tile = 64 (grid.y = NB/64).
// indirect=1: A rows are feature_maps rows addressed by compact-token decode.
// ---------------------------------------------------------------------------
__global__ void __launch_bounds__(256) gemm_kernel(
    const float* __restrict__ A, const float* __restrict__ B,
    const float* __restrict__ bias, float* __restrict__ C,
    int NB, int ldc, int col0, int indirect)
{
    __shared__ float As[16][65];
    __shared__ float Bs[16][68];
    __shared__ int   rowOff[64];

    const int tid = threadIdx.x;
    const int m0  = blockIdx.x * 64;
    const int n0  = blockIdx.y * 64;

    if (tid < 64) {
        int m = m0 + tid;
        if (indirect) {
            int b = m / TOKB, r = m - b * TOKB;
            int off;
            if (r < 4096)      { int y = r >> 6,           x = r & 63;          off = (((b*64+y)*64+x)*4+0)*256; }
            else if (r < 5120) { int r2 = r-4096; int y = r2 >> 5, x = r2 & 31; off = (((b*64+y)*64+x)*4+1)*256; }
            else if (r < 5376) { int r2 = r-5120; int y = r2 >> 4, x = r2 & 15; off = (((b*64+y)*64+x)*4+2)*256; }
            else               { int r2 = r-5376; int y = r2 >> 3, x = r2 & 7;  off = (((b*64+y)*64+x)*4+3)*256; }
            rowOff[tid] = off;
        } else {
            rowOff[tid] = m * 256;
        }
    }
    __syncthreads();

    const int ar = tid >> 2,  ak = (tid & 3)  << 2;   // A loader: row 0..63, k 0/4/8/12
    const int bk = tid >> 4,  bn = (tid & 15) << 2;   // B loader: k 0..15, n 0..60
    const int ty = tid >> 4,  tx = tid & 15;

    float acc[4][4] = {};

    for (int k0 = 0; k0 < 256; k0 += 16) {
        float4 av = *reinterpret_cast<const float4*>(A + rowOff[ar] + k0 + ak);
        As[ak + 0][ar] = av.x;
        As[ak + 1][ar] = av.y;
        As[ak + 2][ar] = av.z;
        As[ak + 3][ar] = av.w;
        float4 bv = *reinterpret_cast<const float4*>(B + (size_t)(k0 + bk) * NB + n0 + bn);
        *reinterpret_cast<float4*>(&Bs[bk][bn]) = bv;
        __syncthreads();
        #pragma unroll
        for (int k = 0; k < 16; k++) {
            float4 bq = *reinterpret_cast<const float4*>(&Bs[k][tx << 2]);
            float a0 = As[k][(ty << 2) + 0];
            float a1 = As[k][(ty << 2) + 1];
            float a2 = As[k][(ty << 2) + 2];
            float a3 = As[k][(ty << 2) + 3];
            acc[0][0] += a0 * bq.x; acc[0][1] += a0 * bq.y; acc[0][2] += a0 * bq.z; acc[0][3] += a0 * bq.w;
            acc[1][0] += a1 * bq.x; acc[1][1] += a1 * bq.y; acc[1][2] += a1 * bq.z; acc[1][3] += a1 * bq.w;
            acc[2][0] += a2 * bq.x; acc[2][1] += a2 * bq.y; acc[2][2] += a2 * bq.z; acc[2][3] += a2 * bq.w;
            acc[3][0] += a3 * bq.x; acc[3][1] += a3 * bq.y; acc[3][2] += a3 * bq.z; acc[3][3] += a3 * bq.w;
        }
        __syncthreads();
    }

    #pragma unroll
    for (int i = 0; i < 4; i++) {
        size_t row = (size_t)(m0 + (ty << 2) + i);
        #pragma unroll
        for (int j = 0; j < 4; j++) {
            int col = n0 + (tx << 2) + j;
            C[row * (size_t)ldc + col0 + col] = acc[i][j] + bias[col];
        }
    }
}

// ---------------------------------------------------------------------------
// Sampling: one block per query (256 threads), one warp per head, lane = hd ch.
// Softmax over 16 (P*L) logits per head, then 16-point bilinear gather.
// ---------------------------------------------------------------------------
__global__ void __launch_bounds__(256) sample_kernel(
    const float* __restrict__ offattw,
    const float* __restrict__ values,
    const float* __restrict__ qpos,
    const int*   __restrict__ qlvl,
    const int*   __restrict__ qbo,
    float* __restrict__ out)
{
    const int q    = blockIdx.x;
    const int warp = threadIdx.x >> 5;   // head
    const int lane = threadIdx.x & 31;   // hd channel

    __shared__ float s_scaled[NLEV][2];
    __shared__ int   s_b;

    if (threadIdx.x == 0) {
        int b = 0;
        #pragma unroll
        for (int i = 0; i < 1; i++) { }  // BATCH=2: single comparison below
        while (b + 1 < 2 && qbo[b + 1] <= q) b++;
        if (qbo[b + 1] <= q) b++;        // generic guard (BATCH=2)
        s_b = (qbo[1] <= q) ? 1 : 0;
    }
    if (threadIdx.x < 8) {
        int l = threadIdx.x >> 1, c = threadIdx.x & 1;
        int ql = qlvl[q];
        float shp_q = (float)(64 >> ql);
        float shp_l = (float)(64 >> l);
        // Match reference rounding: (pos / shape_q) * shape_l
        s_scaled[l][c] = (qpos[q * 2 + c] / shp_q) * shp_l;
    }
    __syncthreads();

    const int h = warp;
    const float* oa = offattw + (size_t)q * 384;

    // softmax over the 16 (p,l) logits for this head (duplicated in both warp halves)
    int i16 = lane & 15;
    float a = oa[256 + i16 * 8 + h];
    float mx = a;
    #pragma unroll
    for (int j = 8; j >= 1; j >>= 1) mx = fmaxf(mx, __shfl_xor_sync(0xffffffffu, mx, j));
    float e = expf(a - mx);
    float s = e;
    #pragma unroll
    for (int j = 8; j >= 1; j >>= 1) s += __shfl_xor_sync(0xffffffffu, s, j);
    float wgt = e / s;

    const int b = s_b;
    float acc = 0.0f;

    #pragma unroll
    for (int i = 0; i < 16; i++) {
        const int l  = i & 3;          // i = p*NLEV + l
        const int Wl = 64 >> l;        // square levels
        float offh = oa[(i * 8 + h) * 2 + 0];
        float offw = oa[(i * 8 + h) * 2 + 1];
        float Hf = (float)Wl;
        float hf = fminf(fmaxf(s_scaled[l][0] + offh, 0.0f), Hf);
        float wf = fminf(fmaxf(s_scaled[l][1] + offw, 0.0f), Hf);
        float h0f = floorf(hf), w0f = floorf(wf);
        float fh = hf - h0f,    fw = wf - w0f;
        int h0 = (int)h0f, w0 = (int)w0f;

        float aw = __shfl_sync(0xffffffffu, wgt, i);

        const float* vbase = values + ((size_t)(b * TOKB + c_loff[l])) * EMB + h * HD + lane;
        bool h0ok = h0 < Wl;
        bool h1ok = (h0 + 1) < Wl;
        bool w0ok = w0 < Wl;
        bool w1ok = (w0 + 1) < Wl;

        float v00 = (h0ok && w0ok) ? vbase[(size_t)(h0 * Wl + w0)       * EMB] : 0.0f;
        float v01 = (h0ok && w1ok) ? vbase[(size_t)(h0 * Wl + w0 + 1)   * EMB] : 0.0f;
        float v10 = (h1ok && w0ok) ? vbase[(size_t)((h0+1) * Wl + w0)   * EMB] : 0.0f;
        float v11 = (h1ok && w1ok) ? vbase[(size_t)((h0+1) * Wl + w0+1) * EMB] : 0.0f;

        float bil = (1.0f - fh) * (1.0f - fw) * v00
                  + (1.0f - fh) * fw          * v01
                  + fh          * (1.0f - fw) * v10
                  + fh          * fw          * v11;
        acc += aw * bil;
    }

    out[(size_t)q * EMB + h * HD + lane] = acc;
}

// ---------------------------------------------------------------------------
extern "C" void kernel_launch(void* const* d_in, const int* in_sizes, int n_in,
                              void* d_out, int out_size)
{
    const float* query  = (const float*)d_in[0];
    const float* qpos   = (const float*)d_in[1];
    const int*   qbo    = (const int*)  d_in[2];
    const float* fm     = (const float*)d_in[3];
    // d_in[4] = level_spatial_shapes (compile-time constants here)
    const int*   qlvl   = (const int*)  d_in[5];
    const float* W_off  = (const float*)d_in[6];
    const float* b_off  = (const float*)d_in[7];
    const float* W_attn = (const float*)d_in[8];
    const float* b_attn = (const float*)d_in[9];
    const float* W_val  = (const float*)d_in[10];
    const float* b_val  = (const float*)d_in[11];
    const float* W_out  = (const float*)d_in[12];
    const float* b_out  = (const float*)d_in[13];
    float* out = (float*)d_out;

    float *gv, *goa, *gao;
    cudaGetSymbolAddress((void**)&gv,  g_values);
    cudaGetSymbolAddress((void**)&goa, g_offattw);
    cudaGetSymbolAddress((void**)&gao, g_attn_out);

    dim3 blk(256);
    // 1) compact values projection: [10880 x 256] = fm_rows @ W_val + b_val
    gemm_kernel<<<dim3(NQ / 64, 4), blk>>>(fm, W_val, b_val, gv, 256, 256, 0, 1);
    // 2) offsets: [10880 x 256] = query @ W_off + b_off   -> cols [0,256) of offattw
    gemm_kernel<<<dim3(NQ / 64, 4), blk>>>(query, W_off, b_off, goa, 256, 384, 0, 0);
    // 3) attn logits: [10880 x 128] = query @ W_attn + b_attn -> cols [256,384)
    gemm_kernel<<<dim3(NQ / 64, 2), blk>>>(query, W_attn, b_attn, goa, 128, 384, 256, 0);
    // 4) softmax + bilinear sampling + head-weighted accumulation
    sample_kernel<<<NQ, 256>>>(goa, gv, qpos, qlvl, qbo, gao);
    // 5) output projection: d_out = attn_out @ W_out + b_out
    gemm_kernel<<<dim3(NQ / 64, 4), blk>>>(gao, W_out, b_out, out, 256, 256, 0, 0);
}

// round 5
// speedup vs baseline: 1.4989x; 1.4989x over previous
#include <cuda_runtime.h>

// Problem constants (fixed by the dataset)
#define NQ      10880          // total queries = BATCH * tok_per_img
#define TOKB    5440           // valid tokens per image (4096+1024+256+64)
#define EMB     256
#define NHEADS  8
#define HD      32
#define NLEV    4
#define NPTS    4

// Scratch (device globals — no allocation allowed)
__device__ float g_values[2 * TOKB * EMB];      // compact projected values  [b][tok][h*32+d]
__device__ float g_offattw[NQ * 384];           // per-query: 256 offsets | 128 attn logits
__device__ float g_attn_out[NQ * EMB];          // per-query sampled+weighted output

__constant__ int c_loff[4] = {0, 4096, 5120, 5376};

// ---------------------------------------------------------------------------
// 128x128 fp32 GEMM tile, 256 threads, 8x8 per thread, K=256 in steps of 8,
// register-staged double-buffered shared memory (one __syncthreads per step).
// indirect=1: A rows are feature_maps rows addressed by compact-token decode.
// ---------------------------------------------------------------------------
__device__ __forceinline__ void gemm_tile(
    const float* __restrict__ A, const float* __restrict__ B,
    const float* __restrict__ bias, float* __restrict__ C,
    int NB, int ldc, int col0, int indirect, int m0, int n0)
{
    __shared__ float As[2][8][128];
    __shared__ float Bs[2][8][128];
    __shared__ int   rowOff[128];

    const int tid = threadIdx.x;

    if (tid < 128) {
        int m = m0 + tid;
        int off;
        if (indirect) {
            int b = (m >= TOKB) ? 1 : 0;
            int r = m - b * TOKB;
            if (r < 4096)      { int y = r >> 6,            x = r & 63;          off = (((b*64+y)*64+x)*4+0)*256; }
            else if (r < 5120) { int r2 = r-4096; int y = r2 >> 5, x = r2 & 31;  off = (((b*64+y)*64+x)*4+1)*256; }
            else if (r < 5376) { int r2 = r-5120; int y = r2 >> 4, x = r2 & 15;  off = (((b*64+y)*64+x)*4+2)*256; }
            else               { int r2 = r-5376; int y = r2 >> 3, x = r2 & 7;   off = (((b*64+y)*64+x)*4+3)*256; }
        } else {
            off = m * 256;
        }
        rowOff[tid] = off;
    }
    __syncthreads();

    const int arow = tid >> 1, akk = (tid & 1) << 2;   // A loader: row 0..127, k 0/4
    const int bkk  = tid >> 5, bnn = (tid & 31) << 2;  // B loader: k 0..7, n 0..124
    const int tx = tid & 15,   ty = tid >> 4;

    float acc[8][8] = {};

    const float* Aptr = A + rowOff[arow] + akk;
    const float* Bptr = B + bkk * NB + n0 + bnn;

    float4 aReg = *reinterpret_cast<const float4*>(Aptr);
    float4 bReg = *reinterpret_cast<const float4*>(Bptr);

    #pragma unroll 1
    for (int it = 0; it < 32; ++it) {
        const int cur = it & 1;
        As[cur][akk + 0][arow] = aReg.x;
        As[cur][akk + 1][arow] = aReg.y;
        As[cur][akk + 2][arow] = aReg.z;
        As[cur][akk + 3][arow] = aReg.w;
        *reinterpret_cast<float4*>(&Bs[cur][bkk][bnn]) = bReg;
        __syncthreads();
        if (it < 31) {
            aReg = *reinterpret_cast<const float4*>(Aptr + (it + 1) * 8);
            bReg = *reinterpret_cast<const float4*>(Bptr + (it + 1) * 8 * NB);
        }
        #pragma unroll
        for (int k = 0; k < 8; ++k) {
            float4 a0 = *reinterpret_cast<const float4*>(&As[cur][k][ty << 2]);
            float4 a1 = *reinterpret_cast<const float4*>(&As[cur][k][64 + (ty << 2)]);
            float4 b0 = *reinterpret_cast<const float4*>(&Bs[cur][k][tx << 2]);
            float4 b1 = *reinterpret_cast<const float4*>(&Bs[cur][k][64 + (tx << 2)]);
            float ar_[8] = {a0.x, a0.y, a0.z, a0.w, a1.x, a1.y, a1.z, a1.w};
            float br_[8] = {b0.x, b0.y, b0.z, b0.w, b1.x, b1.y, b1.z, b1.w};
            #pragma unroll
            for (int i = 0; i < 8; ++i)
                #pragma unroll
                for (int j = 0; j < 8; ++j)
                    acc[i][j] += ar_[i] * br_[j];
        }
    }

    #pragma unroll
    for (int ih = 0; ih < 2; ++ih) {
        #pragma unroll
        for (int i = 0; i < 4; ++i) {
            int row = m0 + ih * 64 + (ty << 2) + i;
            float* crow = C + (size_t)row * ldc + col0 + n0;
            #pragma unroll
            for (int jh = 0; jh < 2; ++jh) {
                int col = jh * 64 + (tx << 2);
                float4 v;
                v.x = acc[ih * 4 + i][jh * 4 + 0] + bias[n0 + col + 0];
                v.y = acc[ih * 4 + i][jh * 4 + 1] + bias[n0 + col + 1];
                v.z = acc[ih * 4 + i][jh * 4 + 2] + bias[n0 + col + 2];
                v.w = acc[ih * 4 + i][jh * 4 + 3] + bias[n0 + col + 3];
                *reinterpret_cast<float4*>(crow + col) = v;
            }
        }
    }
}

// Fused launch for the three independent input-side GEMMs:
//   y=0,1 : values  = fm_rows @ W_val  + b_val   (indirect A rows)  -> g_values
//   y=2,3 : offsets = query  @ W_off  + b_off                       -> g_offattw[:, 0:256)
//   y=4   : logits  = query  @ W_attn + b_attn                      -> g_offattw[:, 256:384)
__global__ void __launch_bounds__(256, 2) gemm_fused_kernel(
    const float* __restrict__ query, const float* __restrict__ fm,
    const float* __restrict__ W_val,  const float* __restrict__ b_val,  float* __restrict__ gv,
    const float* __restrict__ W_off,  const float* __restrict__ b_off,
    const float* __restrict__ W_attn, const float* __restrict__ b_attn, float* __restrict__ goa)
{
    const int m0 = blockIdx.x * 128;
    const int y  = blockIdx.y;
    if (y < 2)       gemm_tile(fm,    W_val,  b_val,  gv,  256, 256, 0,   1, m0, y * 128);
    else if (y < 4)  gemm_tile(query, W_off,  b_off,  goa, 256, 384, 0,   0, m0, (y - 2) * 128);
    else             gemm_tile(query, W_attn, b_attn, goa, 128, 384, 256, 0, m0, 0);
}

// Output projection: d_out = attn_out @ W_out + b_out
__global__ void __launch_bounds__(256, 2) gemm_out_kernel(
    const float* __restrict__ A, const float* __restrict__ B,
    const float* __restrict__ bias, float* __restrict__ C)
{
    gemm_tile(A, B, bias, C, 256, 256, 0, 0, blockIdx.x * 128, blockIdx.y * 128);
}

// ---------------------------------------------------------------------------
// Sampling: one block per query (256 threads), one warp per head, lane = hd ch.
// Softmax over 16 (P*L) logits per head, then 16-point bilinear gather.
// Instruction-lean version: lane-parallel offset loads + shfl, 32-bit indexing,
// lerp-form bilinear, __expf.
// ---------------------------------------------------------------------------
__global__ void __launch_bounds__(256) sample_kernel(
    const float* __restrict__ offattw,
    const float* __restrict__ values,
    const float* __restrict__ qpos,
    const int*   __restrict__ qlvl,
    const int*   __restrict__ qbo,
    float* __restrict__ out)
{
    const int q    = blockIdx.x;
    const int h    = threadIdx.x >> 5;   // head
    const int lane = threadIdx.x & 31;   // hd channel

    __shared__ float s_scaled[NLEV][2];
    __shared__ int   s_b;

    if (threadIdx.x == 0) {
        s_b = (qbo[1] <= q) ? 1 : 0;
    }
    if (threadIdx.x < 8) {
        int l = threadIdx.x >> 1, c = threadIdx.x & 1;
        int ql = qlvl[q];
        float shp_q = (float)(64 >> ql);
        float shp_l = (float)(64 >> l);
        // Match reference rounding: (pos / shape_q) * shape_l
        s_scaled[l][c] = (qpos[q * 2 + c] / shp_q) * shp_l;
    }
    __syncthreads();

    const float* oa = offattw + q * 384;

    // softmax over the 16 (p,l) logits for this head (duplicated in warp halves)
    const int i16 = lane & 15;
    float a = oa[256 + i16 * 8 + h];
    float mx = a;
    #pragma unroll
    for (int j = 8; j >= 1; j >>= 1) mx = fmaxf(mx, __shfl_xor_sync(0xffffffffu, mx, j));
    float e = __expf(a - mx);
    float s = e;
    #pragma unroll
    for (int j = 8; j >= 1; j >>= 1) s += __shfl_xor_sync(0xffffffffu, s, j);
    float wgt = e / s;

    // lane i holds the (offh, offw) pair for flat point index i (duplicated halves)
    float2 off2 = *reinterpret_cast<const float2*>(oa + (i16 * 8 + h) * 2);

    const int b = s_b;
    const int base = (b * TOKB) * EMB + h * HD + lane;
    float acc = 0.0f;

    #pragma unroll
    for (int l = 0; l < NLEV; ++l) {
        const int   sh = 6 - l;
        const int   Wl = 64 >> l;
        const float Hf = (float)Wl;
        const float sc_h = s_scaled[l][0];
        const float sc_w = s_scaled[l][1];
        const float* vb = values + base + c_loff[l] * EMB;
        const int rowStep = Wl << 8;    // one grid row in floats (Wl * EMB)

        #pragma unroll
        for (int p = 0; p < NPTS; ++p) {
            const int i = p * NLEV + l;
            float offh = __shfl_sync(0xffffffffu, off2.x, i);
            float offw = __shfl_sync(0xffffffffu, off2.y, i);
            float aw   = __shfl_sync(0xffffffffu, wgt,   i);

            float hf = fminf(fmaxf(sc_h + offh, 0.0f), Hf);
            float wf = fminf(fmaxf(sc_w + offw, 0.0f), Hf);
            float h0f = floorf(hf), w0f = floorf(wf);
            float fh = hf - h0f,    fw = wf - w0f;
            int h0 = (int)h0f, w0 = (int)w0f;

            bool h0ok = h0 < Wl;
            bool h1ok = (h0 + 1) < Wl;
            bool w0ok = w0 < Wl;
            bool w1ok = (w0 + 1) < Wl;

            int idx = ((h0 << sh) + w0) << 8;   // * EMB

            float v00 = (h0ok && w0ok) ? vb[idx]                 : 0.0f;
            float v01 = (h0ok && w1ok) ? vb[idx + EMB]           : 0.0f;
            float v10 = (h1ok && w0ok) ? vb[idx + rowStep]       : 0.0f;
            float v11 = (h1ok && w1ok) ? vb[idx + rowStep + EMB] : 0.0f;

            float top = v00 + fw * (v01 - v00);
            float bot = v10 + fw * (v11 - v10);
            acc += aw * (top + fh * (bot - top));
        }
    }

    out[q * EMB + h * HD + lane] = acc;
}

// ---------------------------------------------------------------------------
extern "C" void kernel_launch(void* const* d_in, const int* in_sizes, int n_in,
                              void* d_out, int out_size)
{
    const float* query  = (const float*)d_in[0];
    const float* qpos   = (const float*)d_in[1];
    const int*   qbo    = (const int*)  d_in[2];
    const float* fm     = (const float*)d_in[3];
    // d_in[4] = level_spatial_shapes (compile-time constants here)
    const int*   qlvl   = (const int*)  d_in[5];
    const float* W_off  = (const float*)d_in[6];
    const float* b_off  = (const float*)d_in[7];
    const float* W_attn = (const float*)d_in[8];
    const float* b_attn = (const float*)d_in[9];
    const float* W_val  = (const float*)d_in[10];
    const float* b_val  = (const float*)d_in[11];
    const float* W_out  = (const float*)d_in[12];
    const float* b_out  = (const float*)d_in[13];
    float* out = (float*)d_out;

    float *gv, *goa, *gao;
    cudaGetSymbolAddress((void**)&gv,  g_values);
    cudaGetSymbolAddress((void**)&goa, g_offattw);
    cudaGetSymbolAddress((void**)&gao, g_attn_out);

    dim3 blk(256);
    // 1) fused input-side GEMMs: values (indirect), offsets, attn logits
    gemm_fused_kernel<<<dim3(NQ / 128, 5), blk>>>(
        query, fm, W_val, b_val, gv, W_off, b_off, W_attn, b_attn, goa);
    // 2) softmax + bilinear sampling + head-weighted accumulation
    sample_kernel<<<NQ, 256>>>(goa, gv, qpos, qlvl, qbo, gao);
    // 3) output projection: d_out = attn_out @ W_out + b_out
    gemm_out_kernel<<<dim3(NQ / 128, 2), blk>>>(gao, W_out, b_out, out);
}

// round 6
// speedup vs baseline: 1.7085x; 1.1398x over previous
#include <cuda_runtime.h>

// Problem constants (fixed by the dataset)
#define NQ      10880          // total queries = BATCH * tok_per_img
#define TOKB    5440           // valid tokens per image (4096+1024+256+64)
#define EMB     256
#define NHEADS  8
#define HD      32
#define NLEV    4
#define NPTS    4

// Scratch (device globals — no allocation allowed)
__device__ float g_values[2 * TOKB * EMB];      // compact projected values  [b][tok][h*32+d]
__device__ float g_offattw[NQ * 384];           // per-query: 256 offsets | 128 attn logits
__device__ float g_attn_out[NQ * EMB];          // per-query sampled+weighted output

__constant__ int c_loff[4] = {0, 4096, 5120, 5376};

// ---------------------------------------------------------------------------
// Packed fp32x2 helpers (sm_10x: fma.rn.f32x2 — PTX-only, doubles fp32 rate)
// ---------------------------------------------------------------------------
__device__ __forceinline__ unsigned long long pack2(float x, float y) {
    unsigned long long r;
    asm("mov.b64 %0, {%1, %2};" : "=l"(r) : "f"(x), "f"(y));
    return r;
}
__device__ __forceinline__ void fma2(unsigned long long& d,
                                     unsigned long long a, unsigned long long b) {
    asm("fma.rn.f32x2 %0, %1, %2, %0;" : "+l"(d) : "l"(a), "l"(b));
}
__device__ __forceinline__ float2 unpack2(unsigned long long v) {
    float2 f;
    asm("mov.b64 {%0, %1}, %2;" : "=f"(f.x), "=f"(f.y) : "l"(v));
    return f;
}

// ---------------------------------------------------------------------------
// 128x128 fp32 GEMM tile, 256 threads, 8x8 per thread (f32x2-packed along n),
// K=256 in steps of 8, register-staged double-buffered shared memory.
// indirect=1: A rows are feature_maps rows addressed by compact-token decode.
// ---------------------------------------------------------------------------
__device__ __forceinline__ void gemm_tile(
    const float* __restrict__ A, const float* __restrict__ B,
    const float* __restrict__ bias, float* __restrict__ C,
    int NB, int ldc, int col0, int indirect, int m0, int n0)
{
    __shared__ __align__(16) float As[2][8][128];
    __shared__ __align__(16) float Bs[2][8][128];
    __shared__ int rowOff[128];

    const int tid = threadIdx.x;

    if (tid < 128) {
        int m = m0 + tid;
        int off;
        if (indirect) {
            int b = (m >= TOKB) ? 1 : 0;
            int r = m - b * TOKB;
            if (r < 4096)      { int y = r >> 6,            x = r & 63;          off = (((b*64+y)*64+x)*4+0)*256; }
            else if (r < 5120) { int r2 = r-4096; int y = r2 >> 5, x = r2 & 31;  off = (((b*64+y)*64+x)*4+1)*256; }
            else if (r < 5376) { int r2 = r-5120; int y = r2 >> 4, x = r2 & 15;  off = (((b*64+y)*64+x)*4+2)*256; }
            else               { int r2 = r-5376; int y = r2 >> 3, x = r2 & 7;   off = (((b*64+y)*64+x)*4+3)*256; }
        } else {
            off = m * 256;
        }
        rowOff[tid] = off;
    }
    __syncthreads();

    const int arow = tid >> 1, akk = (tid & 1) << 2;   // A loader: row 0..127, k 0/4
    const int bkk  = tid >> 5, bnn = (tid & 31) << 2;  // B loader: k 0..7, n 0..124
    const int tx = tid & 15,   ty = tid >> 4;

    // acc2[i][jp]: row i (8), packed col-pair jp (4) -> 8x8 scalar tile
    unsigned long long acc2[8][4] = {};

    const float* Aptr = A + rowOff[arow] + akk;
    const float* Bptr = B + bkk * NB + n0 + bnn;

    float4 aReg = *reinterpret_cast<const float4*>(Aptr);
    float4 bReg = *reinterpret_cast<const float4*>(Bptr);

    #pragma unroll 1
    for (int it = 0; it < 32; ++it) {
        const int cur = it & 1;
        As[cur][akk + 0][arow] = aReg.x;
        As[cur][akk + 1][arow] = aReg.y;
        As[cur][akk + 2][arow] = aReg.z;
        As[cur][akk + 3][arow] = aReg.w;
        *reinterpret_cast<float4*>(&Bs[cur][bkk][bnn]) = bReg;
        __syncthreads();
        if (it < 31) {
            aReg = *reinterpret_cast<const float4*>(Aptr + (it + 1) * 8);
            bReg = *reinterpret_cast<const float4*>(Bptr + (it + 1) * 8 * NB);
        }
        #pragma unroll
        for (int k = 0; k < 8; ++k) {
            float4 a0 = *reinterpret_cast<const float4*>(&As[cur][k][ty << 2]);
            float4 a1 = *reinterpret_cast<const float4*>(&As[cur][k][64 + (ty << 2)]);
            // B pairs come packed straight out of shared memory (LDS.128)
            ulonglong2 bq0 = *reinterpret_cast<const ulonglong2*>(&Bs[cur][k][tx << 2]);
            ulonglong2 bq1 = *reinterpret_cast<const ulonglong2*>(&Bs[cur][k][64 + (tx << 2)]);
            unsigned long long bb[4] = {bq0.x, bq0.y, bq1.x, bq1.y};
            float ar_[8] = {a0.x, a0.y, a0.z, a0.w, a1.x, a1.y, a1.z, a1.w};
            #pragma unroll
            for (int i = 0; i < 8; ++i) {
                unsigned long long aa = pack2(ar_[i], ar_[i]);
                #pragma unroll
                for (int jp = 0; jp < 4; ++jp)
                    fma2(acc2[i][jp], aa, bb[jp]);
            }
        }
        __syncthreads();
    }

    #pragma unroll
    for (int ih = 0; ih < 2; ++ih) {
        #pragma unroll
        for (int i = 0; i < 4; ++i) {
            int row = m0 + ih * 64 + (ty << 2) + i;
            float* crow = C + (size_t)row * ldc + col0 + n0;
            #pragma unroll
            for (int jh = 0; jh < 2; ++jh) {
                int col = jh * 64 + (tx << 2);
                float2 p0 = unpack2(acc2[ih * 4 + i][jh * 2 + 0]);
                float2 p1 = unpack2(acc2[ih * 4 + i][jh * 2 + 1]);
                float4 v;
                v.x = p0.x + bias[n0 + col + 0];
                v.y = p0.y + bias[n0 + col + 1];
                v.z = p1.x + bias[n0 + col + 2];
                v.w = p1.y + bias[n0 + col + 3];
                *reinterpret_cast<float4*>(crow + col) = v;
            }
        }
    }
}

// Fused launch for the three independent input-side GEMMs:
//   y=0,1 : values  = fm_rows @ W_val  + b_val   (indirect A rows)  -> g_values
//   y=2,3 : offsets = query  @ W_off  + b_off                       -> g_offattw[:, 0:256)
//   y=4   : logits  = query  @ W_attn + b_attn                      -> g_offattw[:, 256:384)
__global__ void __launch_bounds__(256, 2) gemm_fused_kernel(
    const float* __restrict__ query, const float* __restrict__ fm,
    const float* __restrict__ W_val,  const float* __restrict__ b_val,  float* __restrict__ gv,
    const float* __restrict__ W_off,  const float* __restrict__ b_off,
    const float* __restrict__ W_attn, const float* __restrict__ b_attn, float* __restrict__ goa)
{
    const int m0 = blockIdx.x * 128;
    const int y  = blockIdx.y;
    if (y < 2)       gemm_tile(fm,    W_val,  b_val,  gv,  256, 256, 0,   1, m0, y * 128);
    else if (y < 4)  gemm_tile(query, W_off,  b_off,  goa, 256, 384, 0,   0, m0, (y - 2) * 128);
    else             gemm_tile(query, W_attn, b_attn, goa, 128, 384, 256, 0, m0, 0);
}

// Output projection: d_out = attn_out @ W_out + b_out
__global__ void __launch_bounds__(256, 2) gemm_out_kernel(
    const float* __restrict__ A, const float* __restrict__ B,
    const float* __restrict__ bias, float* __restrict__ C)
{
    gemm_tile(A, B, bias, C, 256, 256, 0, 0, blockIdx.x * 128, blockIdx.y * 128);
}

// ---------------------------------------------------------------------------
// Sampling (vectorized 4x): block = 256 threads = 4 queries x 64 threads.
// Per query: 8 heads x 8 lanes; each lane owns 4 channels (float4 gathers).
// Softmax over 16 (P*L) logits per head via width-8 segment shuffles
// (2 logits per lane). Per-point weight/offset via compile-time-selected shfl.
// ---------------------------------------------------------------------------
__global__ void __launch_bounds__(256) sample_kernel(
    const float* __restrict__ offattw,
    const float* __restrict__ values,
    const float* __restrict__ qpos,
    const int*   __restrict__ qlvl,
    const int*   __restrict__ qbo,
    float* __restrict__ out)
{
    const int tid = threadIdx.x;
    const int q0  = blockIdx.x * 4;
    const int qi  = tid >> 6;            // query slot in block (0..3)
    const int q   = q0 + qi;
    const int tq  = tid & 63;            // thread within query
    const int h   = tq >> 3;             // head (0..7)
    const int lg  = tq & 7;              // lane in head group; channels lg*4..lg*4+3

    __shared__ float s_scaled[4][NLEV][2];
    __shared__ int   s_b[4];

    if (tid < 32) {
        int qi2 = tid >> 3, idx = tid & 7;
        int l = idx >> 1, c = idx & 1;
        int qq = q0 + qi2;
        int ql = qlvl[qq];
        float shp_q = (float)(64 >> ql);
        float shp_l = (float)(64 >> l);
        // Match reference rounding: (pos / shape_q) * shape_l
        s_scaled[qi2][l][c] = (qpos[qq * 2 + c] / shp_q) * shp_l;
    }
    if (tid < 4) {
        s_b[tid] = (qbo[1] <= q0 + tid) ? 1 : 0;
    }
    __syncthreads();

    const float* oa = offattw + q * 384;

    // ---- softmax over 16 logits of this head: 2 logits per lane, 8-lane segs
    float a0 = oa[256 + lg * 16 + h];        // logit for point i = 2*lg
    float a1 = oa[256 + lg * 16 + 8 + h];    // logit for point i = 2*lg+1
    float mx = fmaxf(a0, a1);
    #pragma unroll
    for (int j = 4; j >= 1; j >>= 1) mx = fmaxf(mx, __shfl_xor_sync(0xffffffffu, mx, j, 8));
    float e0 = __expf(a0 - mx);
    float e1 = __expf(a1 - mx);
    float s = e0 + e1;
    #pragma unroll
    for (int j = 4; j >= 1; j >>= 1) s += __shfl_xor_sync(0xffffffffu, s, j, 8);
    float inv = __frcp_rn(s);
    float w0 = e0 * inv;                     // weight of point 2*lg
    float w1 = e1 * inv;                     // weight of point 2*lg+1

    // offsets for the two points this lane owns
    float2 off_a = *reinterpret_cast<const float2*>(oa + (lg * 16 + h) * 2);
    float2 off_b = *reinterpret_cast<const float2*>(oa + (lg * 16 + 8 + h) * 2);

    const int b = s_b[qi];
    const int base = (b * TOKB) * EMB + h * HD + lg * 4;
    float4 acc = {0.0f, 0.0f, 0.0f, 0.0f};
    const float4 zero = {0.0f, 0.0f, 0.0f, 0.0f};

    #pragma unroll
    for (int l = 0; l < NLEV; ++l) {
        const int   sh = 6 - l;
        const int   Wl = 64 >> l;
        const float Hf = (float)Wl;
        const float sc_h = s_scaled[qi][l][0];
        const float sc_w = s_scaled[qi][l][1];
        const float* vb = values + base + c_loff[l] * EMB;
        const int rowStep = Wl << 8;    // one grid row in floats (Wl * EMB)

        #pragma unroll
        for (int p = 0; p < NPTS; ++p) {
            const int i = p * NLEV + l;      // flat point index (compile-time)
            float offh = __shfl_sync(0xffffffffu, (i & 1) ? off_b.x : off_a.x, i >> 1, 8);
            float offw = __shfl_sync(0xffffffffu, (i & 1) ? off_b.y : off_a.y, i >> 1, 8);
            float aw   = __shfl_sync(0xffffffffu, (i & 1) ? w1     : w0,      i >> 1, 8);

            float hf = fminf(fmaxf(sc_h + offh, 0.0f), Hf);
            float wf = fminf(fmaxf(sc_w + offw, 0.0f), Hf);
            float h0f = floorf(hf), w0f = floorf(wf);
            float fh = hf - h0f,    fw = wf - w0f;
            int h0 = (int)h0f, w0i = (int)w0f;

            bool h0ok = h0 < Wl;
            bool h1ok = (h0 + 1) < Wl;
            bool w0ok = w0i < Wl;
            bool w1ok = (w0i + 1) < Wl;

            int idx = ((h0 << sh) + w0i) << 8;   // * EMB

            float4 v00 = (h0ok && w0ok) ? *reinterpret_cast<const float4*>(vb + idx)                 : zero;
            float4 v01 = (h0ok && w1ok) ? *reinterpret_cast<const float4*>(vb + idx + EMB)           : zero;
            float4 v10 = (h1ok && w0ok) ? *reinterpret_cast<const float4*>(vb + idx + rowStep)       : zero;
            float4 v11 = (h1ok && w1ok) ? *reinterpret_cast<const float4*>(vb + idx + rowStep + EMB) : zero;

            float4 top, bot;
            top.x = v00.x + fw * (v01.x - v00.x);
            top.y = v00.y + fw * (v01.y - v00.y);
            top.z = v00.z + fw * (v01.z - v00.z);
            top.w = v00.w + fw * (v01.w - v00.w);
            bot.x = v10.x + fw * (v11.x - v10.x);
            bot.y = v10.y + fw * (v11.y - v10.y);
            bot.z = v10.z + fw * (v11.z - v10.z);
            bot.w = v10.w + fw * (v11.w - v10.w);
            acc.x += aw * (top.x + fh * (bot.x - top.x));
            acc.y += aw * (top.y + fh * (bot.y - top.y));
            acc.z += aw * (top.z + fh * (bot.z - top.z));
            acc.w += aw * (top.w + fh * (bot.w - top.w));
        }
    }

    *reinterpret_cast<float4*>(out + q * EMB + h * HD + lg * 4) = acc;
}

// ---------------------------------------------------------------------------
extern "C" void kernel_launch(void* const* d_in, const int* in_sizes, int n_in,
                              void* d_out, int out_size)
{
    const float* query  = (const float*)d_in[0];
    const float* qpos   = (const float*)d_in[1];
    const int*   qbo    = (const int*)  d_in[2];
    const float* fm     = (const float*)d_in[3];
    // d_in[4] = level_spatial_shapes (compile-time constants here)
    const int*   qlvl   = (const int*)  d_in[5];
    const float* W_off  = (const float*)d_in[6];
    const float* b_off  = (const float*)d_in[7];
    const float* W_attn = (const float*)d_in[8];
    const float* b_attn = (const float*)d_in[9];
    const float* W_val  = (const float*)d_in[10];
    const float* b_val  = (const float*)d_in[11];
    const float* W_out  = (const float*)d_in[12];
    const float* b_out  = (const float*)d_in[13];
    float* out = (float*)d_out;

    float *gv, *goa, *gao;
    cudaGetSymbolAddress((void**)&gv,  g_values);
    cudaGetSymbolAddress((void**)&goa, g_offattw);
    cudaGetSymbolAddress((void**)&gao, g_attn_out);

    dim3 blk(256);
    // 1) fused input-side GEMMs: values (indirect), offsets, attn logits
    gemm_fused_kernel<<<dim3(NQ / 128, 5), blk>>>(
        query, fm, W_val, b_val, gv, W_off, b_off, W_attn, b_attn, goa);
    // 2) softmax + bilinear sampling + head-weighted accumulation
    sample_kernel<<<NQ / 4, 256>>>(goa, gv, qpos, qlvl, qbo, gao);
    // 3) output projection: d_out = attn_out @ W_out + b_out
    gemm_out_kernel<<<dim3(NQ / 128, 2), blk>>>(gao, W_out, b_out, out);
}

// round 10
// speedup vs baseline: 2.0376x; 1.1926x over previous
#include <cuda_runtime.h>
#include <cuda_bf16.h>
#include <cstdint>

// Problem constants (fixed by the dataset)
#define NQ      10880          // total queries = BATCH * tok_per_img
#define TOKB    5440           // valid tokens per image (4096+1024+256+64)
#define EMB     256
#define NHEADS  8
#define HD      32
#define NLEV    4
#define NPTS    4

// Scratch (device globals — no allocation allowed)
__device__ float g_values[2 * TOKB * EMB];      // compact projected values
__device__ float g_offattw[NQ * 384];           // per-query: 256 offsets | 128 attn logits
__device__ __nv_bfloat16 g_qhi[NQ * EMB];       // query split
__device__ __nv_bfloat16 g_qlo[NQ * EMB];
__device__ __nv_bfloat16 g_fhi[NQ * EMB];       // gathered feature-map rows split (compact order)
__device__ __nv_bfloat16 g_flo[NQ * EMB];
__device__ __nv_bfloat16 g_shi[NQ * EMB];       // sampled output split
__device__ __nv_bfloat16 g_slo[NQ * EMB];
// Transposed weights W^T[n,k], rows: [0,256)=W_val, [256,512)=W_off, [512,640)=W_attn, [640,896)=W_out
__device__ __nv_bfloat16 g_wthi[896 * 256];
__device__ __nv_bfloat16 g_wtlo[896 * 256];

__constant__ int c_loff[4] = {0, 4096, 5120, 5376};

// ---------------------------------------------------------------------------
// Warp-MMA helpers (sm_80+ base-target PTX: ldmatrix + mma.sync bf16)
// ---------------------------------------------------------------------------
__device__ __forceinline__ uint32_t smem_u32(const void* p) {
    uint32_t a;
    asm("{ .reg .u64 t; cvta.to.shared.u64 t, %1; cvt.u32.u64 %0, t; }" : "=r"(a) : "l"(p));
    return a;
}
__device__ __forceinline__ void ldsm_x4(uint32_t* r, uint32_t addr) {
    asm volatile("ldmatrix.sync.aligned.m8n8.x4.shared.b16 {%0,%1,%2,%3}, [%4];"
        : "=r"(r[0]), "=r"(r[1]), "=r"(r[2]), "=r"(r[3]) : "r"(addr));
}
__device__ __forceinline__ void mma16816(float* c, const uint32_t* a, const uint32_t* b) {
    asm volatile("mma.sync.aligned.m16n8k16.row.col.f32.bf16.bf16.f32 "
        "{%0,%1,%2,%3}, {%4,%5,%6,%7}, {%8,%9}, {%0,%1,%2,%3};"
        : "+f"(c[0]), "+f"(c[1]), "+f"(c[2]), "+f"(c[3])
        : "r"(a[0]), "r"(a[1]), "r"(a[2]), "r"(a[3]), "r"(b[0]), "r"(b[1]));
}

// ---------------------------------------------------------------------------
// fm compact-token row decode (float-element offset into feature_maps)
// ---------------------------------------------------------------------------
__device__ __forceinline__ int fm_row_off(int m) {
    int b = (m >= TOKB) ? 1 : 0;
    int r = m - b * TOKB;
    int off;
    if (r < 4096)      { int y = r >> 6,            x = r & 63;          off = (((b*64+y)*64+x)*4+0)*256; }
    else if (r < 5120) { int r2 = r-4096; int y = r2 >> 5, x = r2 & 31;  off = (((b*64+y)*64+x)*4+1)*256; }
    else if (r < 5376) { int r2 = r-5120; int y = r2 >> 4, x = r2 & 15;  off = (((b*64+y)*64+x)*4+2)*256; }
    else               { int r2 = r-5376; int y = r2 >> 3, x = r2 & 7;   off = (((b*64+y)*64+x)*4+3)*256; }
    return off;
}

// split fp32 -> (hi, lo) bf16 pair, store 4 values as one 8B write each
__device__ __forceinline__ void split_store4(float4 v, __nv_bfloat16* hi, __nv_bfloat16* lo, int p) {
    __nv_bfloat16 h0 = __float2bfloat16(v.x), h1 = __float2bfloat16(v.y),
                  h2 = __float2bfloat16(v.z), h3 = __float2bfloat16(v.w);
    __nv_bfloat16 l0 = __float2bfloat16(v.x - __bfloat162float(h0));
    __nv_bfloat16 l1 = __float2bfloat16(v.y - __bfloat162float(h1));
    __nv_bfloat16 l2 = __float2bfloat16(v.z - __bfloat162float(h2));
    __nv_bfloat16 l3 = __float2bfloat16(v.w - __bfloat162float(h3));
    union { __nv_bfloat162 b[2]; uint2 u; } uh, ul;
    uh.b[0].x = h0; uh.b[0].y = h1; uh.b[1].x = h2; uh.b[1].y = h3;
    ul.b[0].x = l0; ul.b[0].y = l1; ul.b[1].x = l2; ul.b[1].y = l3;
    *reinterpret_cast<uint2*>(hi + p) = uh.u;
    *reinterpret_cast<uint2*>(lo + p) = ul.u;
}

// ---------------------------------------------------------------------------
// Split kernels: fp32 -> bf16 hi/lo
// ---------------------------------------------------------------------------
__global__ void __launch_bounds__(256) split_inputs_kernel(
    const float* __restrict__ query, const float* __restrict__ fm)
{
    int idx = blockIdx.x * 256 + threadIdx.x;    // NQ*64 threads
    int m  = idx >> 6;
    int k4 = (idx & 63) << 2;
    float4 qv = *reinterpret_cast<const float4*>(query + m * EMB + k4);
    split_store4(qv, g_qhi, g_qlo, m * EMB + k4);
    float4 fv = *reinterpret_cast<const float4*>(fm + fm_row_off(m) + k4);
    split_store4(fv, g_fhi, g_flo, m * EMB + k4);
}

__global__ void __launch_bounds__(256) split_w_kernel(
    const float* __restrict__ W_val, const float* __restrict__ W_off,
    const float* __restrict__ W_attn, const float* __restrict__ W_out)
{
    int idx = blockIdx.x * 256 + threadIdx.x;    // 896*256 threads
    int row = idx >> 8, k = idx & 255;
    const float* src; int n, NB;
    if (row < 256)      { src = W_val;  n = row;       NB = 256; }
    else if (row < 512) { src = W_off;  n = row - 256; NB = 256; }
    else if (row < 640) { src = W_attn; n = row - 512; NB = 128; }
    else                { src = W_out;  n = row - 640; NB = 256; }
    float v = src[k * NB + n];
    __nv_bfloat16 h = __float2bfloat16(v);
    g_wthi[row * 256 + k] = h;
    g_wtlo[row * 256 + k] = __float2bfloat16(v - __bfloat162float(h));
}

// ---------------------------------------------------------------------------
// Warp-MMA tile: C[128,128] = A[128,256](hi+lo) @ B(128 W^T rows)(hi+lo) + bias
// Split-fp32: Ahi*Bhi + Ahi*Blo + Alo*Bhi, fp32 accumulate in registers.
// 8 warps as 4(m) x 2(n): each warp 32m x 64n. K staged 64/iter in SW128 smem.
// ---------------------------------------------------------------------------
#define SA_HI 0
#define SA_LO 16384
#define SB_HI 32768
#define SB_LO 49152
#define SM_TOT 65536

__device__ __forceinline__ void mma_tile128(
    const __nv_bfloat16* __restrict__ Ahi, const __nv_bfloat16* __restrict__ Alo,
    const __nv_bfloat16* __restrict__ Bhi, const __nv_bfloat16* __restrict__ Blo,
    const float* __restrict__ bias, float* __restrict__ C,
    int ldc, int cbase, int m0)
{
    extern __shared__ char smem[];
    const uint32_t sb = smem_u32(smem);
    const int tid = threadIdx.x;
    const int wid = tid >> 5, lane = tid & 31;
    const int warp_m = wid & 3, warp_n = wid >> 2;
    const int grp = lane >> 3, l8 = lane & 7;

    float acc[2][8][4];
    #pragma unroll
    for (int mi = 0; mi < 2; ++mi)
        #pragma unroll
        for (int ni = 0; ni < 8; ++ni)
            #pragma unroll
            for (int j = 0; j < 4; ++j) acc[mi][ni][j] = 0.0f;

    const int lr  = tid >> 1;            // staging row 0..127
    const int lc0 = (tid & 1) * 4;       // staging 16B-chunk base (0 or 4)

    // precompute swizzled smem addrs for the fragment loads (vary only with kb)
    const int a_row = warp_m * 32 + (grp & 1) * 8 + l8;     // + mi*16
    const int a_kb0 = (grp >> 1) * 16;
    const int b_row = warp_n * 64 + (grp >> 1) * 8 + l8;    // + pi*16
    const int b_kb0 = (grp & 1) * 16;

    for (int kc = 0; kc < 4; ++kc) {
        // ---- stage K=64 chunk of A(hi/lo) and B(hi/lo) into swizzled smem
        const uint4* gAh = reinterpret_cast<const uint4*>(Ahi + (m0 + lr) * 256 + kc * 64);
        const uint4* gAl = reinterpret_cast<const uint4*>(Alo + (m0 + lr) * 256 + kc * 64);
        const uint4* gBh = reinterpret_cast<const uint4*>(Bhi + lr * 256 + kc * 64);
        const uint4* gBl = reinterpret_cast<const uint4*>(Blo + lr * 256 + kc * 64);
        #pragma unroll
        for (int u = 0; u < 4; ++u) {
            int ch = lc0 + u;
            uint32_t bo = lr * 128 + ch * 16;
            uint32_t so = bo ^ ((bo >> 3) & 0x70);
            *reinterpret_cast<uint4*>(smem + SA_HI + so) = gAh[ch];
            *reinterpret_cast<uint4*>(smem + SA_LO + so) = gAl[ch];
            *reinterpret_cast<uint4*>(smem + SB_HI + so) = gBh[ch];
            *reinterpret_cast<uint4*>(smem + SB_LO + so) = gBl[ch];
        }
        __syncthreads();

        // ---- 4 k16 steps
        #pragma unroll
        for (int s = 0; s < 4; ++s) {
            const int kb = s * 32;
            uint32_t ah[2][4], al[2][4];
            #pragma unroll
            for (int mi = 0; mi < 2; ++mi) {
                uint32_t off = (a_row + mi * 16) * 128 + kb + a_kb0;
                uint32_t so = off ^ ((off >> 3) & 0x70);
                ldsm_x4(ah[mi], sb + SA_HI + so);
                ldsm_x4(al[mi], sb + SA_LO + so);
            }
            uint32_t bh[4][4], bl[4][4];
            #pragma unroll
            for (int pi = 0; pi < 4; ++pi) {
                uint32_t off = (b_row + pi * 16) * 128 + kb + b_kb0;
                uint32_t so = off ^ ((off >> 3) & 0x70);
                ldsm_x4(bh[pi], sb + SB_HI + so);
                ldsm_x4(bl[pi], sb + SB_LO + so);
            }
            #pragma unroll
            for (int mi = 0; mi < 2; ++mi)
                #pragma unroll
                for (int pi = 0; pi < 4; ++pi)
                    #pragma unroll
                    for (int hf = 0; hf < 2; ++hf) {
                        float* c = acc[mi][pi * 2 + hf];
                        mma16816(c, ah[mi], &bh[pi][hf * 2]);
                        mma16816(c, ah[mi], &bl[pi][hf * 2]);
                        mma16816(c, al[mi], &bh[pi][hf * 2]);
                    }
        }
        __syncthreads();
    }

    // ---- epilogue: accumulators -> C (+bias)
    const int rbase = m0 + warp_m * 32 + (lane >> 2);
    const int nc0   = warp_n * 64 + (lane & 3) * 2;
    #pragma unroll
    for (int mi = 0; mi < 2; ++mi) {
        #pragma unroll
        for (int ni = 0; ni < 8; ++ni) {
            int nl = nc0 + ni * 8;
            float b0 = bias[nl], b1 = bias[nl + 1];
            const float* c = acc[mi][ni];
            int r0 = rbase + mi * 16;
            float2 v0 = {c[0] + b0, c[1] + b1};
            float2 v1 = {c[2] + b0, c[3] + b1};
            *reinterpret_cast<float2*>(C + (size_t)r0 * ldc + cbase + nl) = v0;
            *reinterpret_cast<float2*>(C + (size_t)(r0 + 8) * ldc + cbase + nl) = v1;
        }
    }
}

// Fused input-side MMAs: y=0,1 values halves; y=2,3 offsets halves; y=4 attn logits
__global__ void __launch_bounds__(256, 1) mma_fused_kernel(
    const float* __restrict__ b_val, const float* __restrict__ b_off,
    const float* __restrict__ b_attn)
{
    const int m0 = blockIdx.x * 128;
    const int y  = blockIdx.y;
    switch (y) {
    case 0: mma_tile128(g_fhi, g_flo, g_wthi +   0*256, g_wtlo +   0*256, b_val,       g_values,  256,   0, m0); break;
    case 1: mma_tile128(g_fhi, g_flo, g_wthi + 128*256, g_wtlo + 128*256, b_val + 128, g_values,  256, 128, m0); break;
    case 2: mma_tile128(g_qhi, g_qlo, g_wthi + 256*256, g_wtlo + 256*256, b_off,       g_offattw, 384,   0, m0); break;
    case 3: mma_tile128(g_qhi, g_qlo, g_wthi + 384*256, g_wtlo + 384*256, b_off + 128, g_offattw, 384, 128, m0); break;
    default:mma_tile128(g_qhi, g_qlo, g_wthi + 512*256, g_wtlo + 512*256, b_attn,      g_offattw, 384, 256, m0); break;
    }
}

// Output projection MMA: d_out = attn_out @ W_out + b_out
__global__ void __launch_bounds__(256, 1) mma_out_kernel(
    const float* __restrict__ b_out, float* __restrict__ out)
{
    const int m0 = blockIdx.x * 128;
    const int nh = blockIdx.y;
    mma_tile128(g_shi, g_slo, g_wthi + (640 + nh*128)*256, g_wtlo + (640 + nh*128)*256,
                b_out + nh*128, out, 256, nh*128, m0);
}

// ---------------------------------------------------------------------------
// Sampling (vectorized 4x): block = 256 threads = 4 queries x 64 threads.
// Per query: 8 heads x 8 lanes; each lane owns 4 channels (float4 gathers).
// Writes the result pre-split to bf16 hi/lo for the out-projection MMA.
// ---------------------------------------------------------------------------
__global__ void __launch_bounds__(256) sample_kernel(
    const float* __restrict__ qpos,
    const int*   __restrict__ qlvl,
    const int*   __restrict__ qbo)
{
    const int tid = threadIdx.x;
    const int q0  = blockIdx.x * 4;
    const int qi  = tid >> 6;            // query slot in block (0..3)
    const int q   = q0 + qi;
    const int tq  = tid & 63;            // thread within query
    const int h   = tq >> 3;             // head (0..7)
    const int lg  = tq & 7;              // lane in head group; channels lg*4..lg*4+3

    __shared__ float s_scaled[4][NLEV][2];
    __shared__ int   s_b[4];

    if (tid < 32) {
        int qi2 = tid >> 3, idx = tid & 7;
        int l = idx >> 1, c = idx & 1;
        int qq = q0 + qi2;
        int ql = qlvl[qq];
        float shp_q = (float)(64 >> ql);
        float shp_l = (float)(64 >> l);
        s_scaled[qi2][l][c] = (qpos[qq * 2 + c] / shp_q) * shp_l;
    }
    if (tid < 4) {
        s_b[tid] = (qbo[1] <= q0 + tid) ? 1 : 0;
    }
    __syncthreads();

    const float* oa = g_offattw + q * 384;

    // softmax over 16 logits of this head: 2 logits per lane, width-8 segments
    float a0 = oa[256 + lg * 16 + h];
    float a1 = oa[256 + lg * 16 + 8 + h];
    float mx = fmaxf(a0, a1);
    #pragma unroll
    for (int j = 4; j >= 1; j >>= 1) mx = fmaxf(mx, __shfl_xor_sync(0xffffffffu, mx, j, 8));
    float e0 = __expf(a0 - mx);
    float e1 = __expf(a1 - mx);
    float s = e0 + e1;
    #pragma unroll
    for (int j = 4; j >= 1; j >>= 1) s += __shfl_xor_sync(0xffffffffu, s, j, 8);
    float inv = __frcp_rn(s);
    float w0 = e0 * inv;
    float w1 = e1 * inv;

    float2 off_a = *reinterpret_cast<const float2*>(oa + (lg * 16 + h) * 2);
    float2 off_b = *reinterpret_cast<const float2*>(oa + (lg * 16 + 8 + h) * 2);

    const int b = s_b[qi];
    const int base = (b * TOKB) * EMB + h * HD + lg * 4;
    float4 acc = {0.0f, 0.0f, 0.0f, 0.0f};
    const float4 zero = {0.0f, 0.0f, 0.0f, 0.0f};

    #pragma unroll
    for (int l = 0; l < NLEV; ++l) {
        const int   sh = 6 - l;
        const int   Wl = 64 >> l;
        const float Hf = (float)Wl;
        const float sc_h = s_scaled[qi][l][0];
        const float sc_w = s_scaled[qi][l][1];
        const float* vb = g_values + base + c_loff[l] * EMB;
        const int rowStep = Wl << 8;

        #pragma unroll
        for (int p = 0; p < NPTS; ++p) {
            const int i = p * NLEV + l;
            float offh = __shfl_sync(0xffffffffu, (i & 1) ? off_b.x : off_a.x, i >> 1, 8);
            float offw = __shfl_sync(0xffffffffu, (i & 1) ? off_b.y : off_a.y, i >> 1, 8);
            float aw   = __shfl_sync(0xffffffffu, (i & 1) ? w1     : w0,      i >> 1, 8);

            float hf = fminf(fmaxf(sc_h + offh, 0.0f), Hf);
            float wf = fminf(fmaxf(sc_w + offw, 0.0f), Hf);
            float h0f = floorf(hf), w0f = floorf(wf);
            float fh = hf - h0f,    fw = wf - w0f;
            int h0 = (int)h0f, w0i = (int)w0f;

            bool h0ok = h0 < Wl;
            bool h1ok = (h0 + 1) < Wl;
            bool w0ok = w0i < Wl;
            bool w1ok = (w0i + 1) < Wl;

            int idx = ((h0 << sh) + w0i) << 8;

            float4 v00 = (h0ok && w0ok) ? *reinterpret_cast<const float4*>(vb + idx)                 : zero;
            float4 v01 = (h0ok && w1ok) ? *reinterpret_cast<const float4*>(vb + idx + EMB)           : zero;
            float4 v10 = (h1ok && w0ok) ? *reinterpret_cast<const float4*>(vb + idx + rowStep)       : zero;
            float4 v11 = (h1ok && w1ok) ? *reinterpret_cast<const float4*>(vb + idx + rowStep + EMB) : zero;

            float4 top, bot;
            top.x = v00.x + fw * (v01.x - v00.x);
            top.y = v00.y + fw * (v01.y - v00.y);
            top.z = v00.z + fw * (v01.z - v00.z);
            top.w = v00.w + fw * (v01.w - v00.w);
            bot.x = v10.x + fw * (v11.x - v10.x);
            bot.y = v10.y + fw * (v11.y - v10.y);
            bot.z = v10.z + fw * (v11.z - v10.z);
            bot.w = v10.w + fw * (v11.w - v10.w);
            acc.x += aw * (top.x + fh * (bot.x - top.x));
            acc.y += aw * (top.y + fh * (bot.y - top.y));
            acc.z += aw * (top.z + fh * (bot.z - top.z));
            acc.w += aw * (top.w + fh * (bot.w - top.w));
        }
    }

    split_store4(acc, g_shi, g_slo, q * EMB + h * HD + lg * 4);
}

// ---------------------------------------------------------------------------
extern "C" void kernel_launch(void* const* d_in, const int* in_sizes, int n_in,
                              void* d_out, int out_size)
{
    const float* query  = (const float*)d_in[0];
    const float* qpos   = (const float*)d_in[1];
    const int*   qbo    = (const int*)  d_in[2];
    const float* fm     = (const float*)d_in[3];
    // d_in[4] = level_spatial_shapes (compile-time constants here)
    const int*   qlvl   = (const int*)  d_in[5];
    const float* W_off  = (const float*)d_in[6];
    const float* b_off  = (const float*)d_in[7];
    const float* W_attn = (const float*)d_in[8];
    const float* b_attn = (const float*)d_in[9];
    const float* W_val  = (const float*)d_in[10];
    const float* b_val  = (const float*)d_in[11];
    const float* W_out  = (const float*)d_in[12];
    const float* b_out  = (const float*)d_in[13];
    float* out = (float*)d_out;

    static bool attr_done = false;
    if (!attr_done) {
        cudaFuncSetAttribute(mma_fused_kernel, cudaFuncAttributeMaxDynamicSharedMemorySize, SM_TOT);
        cudaFuncSetAttribute(mma_out_kernel,   cudaFuncAttributeMaxDynamicSharedMemorySize, SM_TOT);
        attr_done = true;
    }

    // 1) fp32 -> bf16 hi/lo splits (query, gathered fm rows, transposed weights)
    split_inputs_kernel<<<NQ * 64 / 256, 256>>>(query, fm);
    split_w_kernel<<<896, 256>>>(W_val, W_off, W_attn, W_out);
    // 2) tensor-core MMAs: values projection + offsets + attn logits
    mma_fused_kernel<<<dim3(NQ / 128, 5), 256, SM_TOT>>>(b_val, b_off, b_attn);
    // 3) softmax + bilinear sampling + head-weighted accumulation (writes split)
    sample_kernel<<<NQ / 4, 256>>>(qpos, qlvl, qbo);
    // 4) output projection MMA -> d_out
    mma_out_kernel<<<dim3(NQ / 128, 2), 256, SM_TOT>>>(b_out, out);
}

// round 11
// speedup vs baseline: 2.3029x; 1.1302x over previous
#include <cuda_runtime.h>
#include <cuda_bf16.h>
#include <cstdint>

// Problem constants (fixed by the dataset)
#define NQ      10880          // total queries = BATCH * tok_per_img
#define TOKB    5440           // valid tokens per image (4096+1024+256+64)
#define EMB     256
#define NHEADS  8
#define HD      32
#define NLEV    4
#define NPTS    4

// Scratch (device globals — no allocation allowed)
__device__ float g_values[2 * TOKB * EMB];      // compact projected values
__device__ float g_offattw[NQ * 384];           // per-query: 256 offsets | 128 attn logits
__device__ __nv_bfloat16 g_qhi[NQ * EMB];       // query split
__device__ __nv_bfloat16 g_qlo[NQ * EMB];
__device__ __nv_bfloat16 g_fhi[NQ * EMB];       // gathered feature-map rows split (compact order)
__device__ __nv_bfloat16 g_flo[NQ * EMB];
__device__ __nv_bfloat16 g_shi[NQ * EMB];       // sampled output split
__device__ __nv_bfloat16 g_slo[NQ * EMB];
// Transposed weights W^T[n,k], rows: [0,256)=W_val, [256,512)=W_off, [512,640)=W_attn, [640,896)=W_out
__device__ __nv_bfloat16 g_wthi[896 * 256];
__device__ __nv_bfloat16 g_wtlo[896 * 256];

__constant__ int c_loff[4] = {0, 4096, 5120, 5376};

// ---------------------------------------------------------------------------
// Warp-MMA helpers (sm_80+ base-target PTX: ldmatrix + mma.sync bf16 + cp.async)
// ---------------------------------------------------------------------------
__device__ __forceinline__ uint32_t smem_u32(const void* p) {
    uint32_t a;
    asm("{ .reg .u64 t; cvta.to.shared.u64 t, %1; cvt.u32.u64 %0, t; }" : "=r"(a) : "l"(p));
    return a;
}
__device__ __forceinline__ void ldsm_x4(uint32_t* r, uint32_t addr) {
    asm volatile("ldmatrix.sync.aligned.m8n8.x4.shared.b16 {%0,%1,%2,%3}, [%4];"
        : "=r"(r[0]), "=r"(r[1]), "=r"(r[2]), "=r"(r[3]) : "r"(addr));
}
__device__ __forceinline__ void mma16816(float* c, const uint32_t* a, const uint32_t* b) {
    asm volatile("mma.sync.aligned.m16n8k16.row.col.f32.bf16.bf16.f32 "
        "{%0,%1,%2,%3}, {%4,%5,%6,%7}, {%8,%9}, {%0,%1,%2,%3};"
        : "+f"(c[0]), "+f"(c[1]), "+f"(c[2]), "+f"(c[3])
        : "r"(a[0]), "r"(a[1]), "r"(a[2]), "r"(a[3]), "r"(b[0]), "r"(b[1]));
}
__device__ __forceinline__ void cp16(uint32_t dst, const void* src) {
    asm volatile("cp.async.cg.shared.global [%0], [%1], 16;" :: "r"(dst), "l"(src));
}
__device__ __forceinline__ void cp_commit() {
    asm volatile("cp.async.commit_group;");
}

// ---------------------------------------------------------------------------
// fm compact-token row decode (float-element offset into feature_maps)
// ---------------------------------------------------------------------------
__device__ __forceinline__ int fm_row_off(int m) {
    int b = (m >= TOKB) ? 1 : 0;
    int r = m - b * TOKB;
    int off;
    if (r < 4096)      { int y = r >> 6,            x = r & 63;          off = (((b*64+y)*64+x)*4+0)*256; }
    else if (r < 5120) { int r2 = r-4096; int y = r2 >> 5, x = r2 & 31;  off = (((b*64+y)*64+x)*4+1)*256; }
    else if (r < 5376) { int r2 = r-5120; int y = r2 >> 4, x = r2 & 15;  off = (((b*64+y)*64+x)*4+2)*256; }
    else               { int r2 = r-5376; int y = r2 >> 3, x = r2 & 7;   off = (((b*64+y)*64+x)*4+3)*256; }
    return off;
}

// split fp32 -> (hi, lo) bf16 pair, store 4 values as one 8B write each
__device__ __forceinline__ void split_store4(float4 v, __nv_bfloat16* hi, __nv_bfloat16* lo, int p) {
    __nv_bfloat16 h0 = __float2bfloat16(v.x), h1 = __float2bfloat16(v.y),
                  h2 = __float2bfloat16(v.z), h3 = __float2bfloat16(v.w);
    __nv_bfloat16 l0 = __float2bfloat16(v.x - __bfloat162float(h0));
    __nv_bfloat16 l1 = __float2bfloat16(v.y - __bfloat162float(h1));
    __nv_bfloat16 l2 = __float2bfloat16(v.z - __bfloat162float(h2));
    __nv_bfloat16 l3 = __float2bfloat16(v.w - __bfloat162float(h3));
    union { __nv_bfloat162 b[2]; uint2 u; } uh, ul;
    uh.b[0].x = h0; uh.b[0].y = h1; uh.b[1].x = h2; uh.b[1].y = h3;
    ul.b[0].x = l0; ul.b[0].y = l1; ul.b[1].x = l2; ul.b[1].y = l3;
    *reinterpret_cast<uint2*>(hi + p) = uh.u;
    *reinterpret_cast<uint2*>(lo + p) = ul.u;
}

// ---------------------------------------------------------------------------
// Split kernels: fp32 -> bf16 hi/lo
// ---------------------------------------------------------------------------
__global__ void __launch_bounds__(256) split_inputs_kernel(
    const float* __restrict__ query, const float* __restrict__ fm)
{
    int idx = blockIdx.x * 256 + threadIdx.x;    // NQ*64 threads
    int m  = idx >> 6;
    int k4 = (idx & 63) << 2;
    float4 qv = *reinterpret_cast<const float4*>(query + m * EMB + k4);
    split_store4(qv, g_qhi, g_qlo, m * EMB + k4);
    float4 fv = *reinterpret_cast<const float4*>(fm + fm_row_off(m) + k4);
    split_store4(fv, g_fhi, g_flo, m * EMB + k4);
}

__global__ void __launch_bounds__(256) split_w_kernel(
    const float* __restrict__ W_val, const float* __restrict__ W_off,
    const float* __restrict__ W_attn, const float* __restrict__ W_out)
{
    int idx = blockIdx.x * 256 + threadIdx.x;    // 896*256 threads
    int row = idx >> 8, k = idx & 255;
    const float* src; int n, NB;
    if (row < 256)      { src = W_val;  n = row;       NB = 256; }
    else if (row < 512) { src = W_off;  n = row - 256; NB = 256; }
    else if (row < 640) { src = W_attn; n = row - 512; NB = 128; }
    else                { src = W_out;  n = row - 640; NB = 256; }
    float v = src[k * NB + n];
    __nv_bfloat16 h = __float2bfloat16(v);
    g_wthi[row * 256 + k] = h;
    g_wtlo[row * 256 + k] = __float2bfloat16(v - __bfloat162float(h));
}

// ---------------------------------------------------------------------------
// Warp-MMA tile: C[128,128] = A[128,256](hi+lo) @ B(128 W^T rows)(hi+lo) + bias
// Split-fp32: Ahi*Bhi + Ahi*Blo + Alo*Bhi, fp32 accumulate in registers.
// 8 warps as 4(m) x 2(n): each warp 32m x 64n. K staged 64/iter,
// 2-stage cp.async double buffer (prefetch kc+1 while computing kc).
// ---------------------------------------------------------------------------
#define SA_HI 0
#define SA_LO 16384
#define SB_HI 32768
#define SB_LO 49152
#define STAGE_SZ 65536
#define SM_TOT (2 * STAGE_SZ)

__device__ __forceinline__ void mma_tile128(
    const __nv_bfloat16* __restrict__ Ahi, const __nv_bfloat16* __restrict__ Alo,
    const __nv_bfloat16* __restrict__ Bhi, const __nv_bfloat16* __restrict__ Blo,
    const float* __restrict__ bias, float* __restrict__ C,
    int ldc, int cbase, int m0)
{
    extern __shared__ char smem[];
    const uint32_t sb = smem_u32(smem);
    const int tid = threadIdx.x;
    const int wid = tid >> 5, lane = tid & 31;
    const int warp_m = wid & 3, warp_n = wid >> 2;
    const int grp = lane >> 3, l8 = lane & 7;

    float acc[2][8][4];
    #pragma unroll
    for (int mi = 0; mi < 2; ++mi)
        #pragma unroll
        for (int ni = 0; ni < 8; ++ni)
            #pragma unroll
            for (int j = 0; j < 4; ++j) acc[mi][ni][j] = 0.0f;

    const int lr  = tid >> 1;            // staging row 0..127
    const int lc0 = (tid & 1) * 4;       // staging 16B-chunk base (0 or 4)

    // per-thread source row bases (bytes advance by kc*128 per chunk)
    const char* pAh = reinterpret_cast<const char*>(Ahi + (m0 + lr) * 256);
    const char* pAl = reinterpret_cast<const char*>(Alo + (m0 + lr) * 256);
    const char* pBh = reinterpret_cast<const char*>(Bhi + lr * 256);
    const char* pBl = reinterpret_cast<const char*>(Blo + lr * 256);

    // swizzled destination offsets for the 4 chunks this thread stages
    uint32_t dsto[4];
    #pragma unroll
    for (int u = 0; u < 4; ++u) {
        uint32_t bo = lr * 128 + (lc0 + u) * 16;
        dsto[u] = bo ^ ((bo >> 3) & 0x70);
    }

    // fragment-load address bases
    const int a_row = warp_m * 32 + (grp & 1) * 8 + l8;     // + mi*16
    const int a_kb0 = (grp >> 1) * 16;
    const int b_row = warp_n * 64 + (grp >> 1) * 8 + l8;    // + pi*16
    const int b_kb0 = (grp & 1) * 16;

    // ---- issue stage for chunk kc into buffer (kc&1)
    #define ISSUE(kc) do { \
        uint32_t sbase = sb + ((kc) & 1) * STAGE_SZ; \
        int gb = (kc) * 128; \
        _Pragma("unroll") \
        for (int u = 0; u < 4; ++u) { \
            int co = (lc0 + u) * 16; \
            cp16(sbase + SA_HI + dsto[u], pAh + gb + co); \
            cp16(sbase + SA_LO + dsto[u], pAl + gb + co); \
            cp16(sbase + SB_HI + dsto[u], pBh + gb + co); \
            cp16(sbase + SB_LO + dsto[u], pBl + gb + co); \
        } \
        cp_commit(); \
    } while (0)

    ISSUE(0);

    for (int kc = 0; kc < 4; ++kc) {
        if (kc < 3) ISSUE(kc + 1);
        if (kc < 3) asm volatile("cp.async.wait_group 1;");
        else        asm volatile("cp.async.wait_group 0;");
        __syncthreads();

        const uint32_t stg = sb + (kc & 1) * STAGE_SZ;
        #pragma unroll
        for (int s = 0; s < 4; ++s) {
            const int kb = s * 32;
            uint32_t ah[2][4], al[2][4];
            #pragma unroll
            for (int mi = 0; mi < 2; ++mi) {
                uint32_t off = (a_row + mi * 16) * 128 + kb + a_kb0;
                uint32_t so = off ^ ((off >> 3) & 0x70);
                ldsm_x4(ah[mi], stg + SA_HI + so);
                ldsm_x4(al[mi], stg + SA_LO + so);
            }
            uint32_t bh[4][4], bl[4][4];
            #pragma unroll
            for (int pi = 0; pi < 4; ++pi) {
                uint32_t off = (b_row + pi * 16) * 128 + kb + b_kb0;
                uint32_t so = off ^ ((off >> 3) & 0x70);
                ldsm_x4(bh[pi], stg + SB_HI + so);
                ldsm_x4(bl[pi], stg + SB_LO + so);
            }
            #pragma unroll
            for (int mi = 0; mi < 2; ++mi)
                #pragma unroll
                for (int pi = 0; pi < 4; ++pi)
                    #pragma unroll
                    for (int hf = 0; hf < 2; ++hf) {
                        float* c = acc[mi][pi * 2 + hf];
                        mma16816(c, ah[mi], &bh[pi][hf * 2]);
                        mma16816(c, ah[mi], &bl[pi][hf * 2]);
                        mma16816(c, al[mi], &bh[pi][hf * 2]);
                    }
        }
        __syncthreads();
    }
    #undef ISSUE

    // ---- epilogue: accumulators -> C (+bias)
    const int rbase = m0 + warp_m * 32 + (lane >> 2);
    const int nc0   = warp_n * 64 + (lane & 3) * 2;
    #pragma unroll
    for (int mi = 0; mi < 2; ++mi) {
        #pragma unroll
        for (int ni = 0; ni < 8; ++ni) {
            int nl = nc0 + ni * 8;
            float b0 = bias[nl], b1 = bias[nl + 1];
            const float* c = acc[mi][ni];
            int r0 = rbase + mi * 16;
            float2 v0 = {c[0] + b0, c[1] + b1};
            float2 v1 = {c[2] + b0, c[3] + b1};
            *reinterpret_cast<float2*>(C + (size_t)r0 * ldc + cbase + nl) = v0;
            *reinterpret_cast<float2*>(C + (size_t)(r0 + 8) * ldc + cbase + nl) = v1;
        }
    }
}

// Fused input-side MMAs: y=0,1 values halves; y=2,3 offsets halves; y=4 attn logits
__global__ void __launch_bounds__(256, 1) mma_fused_kernel(
    const float* __restrict__ b_val, const float* __restrict__ b_off,
    const float* __restrict__ b_attn)
{
    const int m0 = blockIdx.x * 128;
    const int y  = blockIdx.y;
    switch (y) {
    case 0: mma_tile128(g_fhi, g_flo, g_wthi +   0*256, g_wtlo +   0*256, b_val,       g_values,  256,   0, m0); break;
    case 1: mma_tile128(g_fhi, g_flo, g_wthi + 128*256, g_wtlo + 128*256, b_val + 128, g_values,  256, 128, m0); break;
    case 2: mma_tile128(g_qhi, g_qlo, g_wthi + 256*256, g_wtlo + 256*256, b_off,       g_offattw, 384,   0, m0); break;
    case 3: mma_tile128(g_qhi, g_qlo, g_wthi + 384*256, g_wtlo + 384*256, b_off + 128, g_offattw, 384, 128, m0); break;
    default:mma_tile128(g_qhi, g_qlo, g_wthi + 512*256, g_wtlo + 512*256, b_attn,      g_offattw, 384, 256, m0); break;
    }
}

// Output projection MMA: d_out = attn_out @ W_out + b_out
__global__ void __launch_bounds__(256, 1) mma_out_kernel(
    const float* __restrict__ b_out, float* __restrict__ out)
{
    const int m0 = blockIdx.x * 128;
    const int nh = blockIdx.y;
    mma_tile128(g_shi, g_slo, g_wthi + (640 + nh*128)*256, g_wtlo + (640 + nh*128)*256,
                b_out + nh*128, out, 256, nh*128, m0);
}

// ---------------------------------------------------------------------------
// Sampling (vectorized 4x): block = 256 threads = 4 queries x 64 threads.
// Per query: 8 heads x 8 lanes; each lane owns 4 channels (float4 gathers).
// Writes the result pre-split to bf16 hi/lo for the out-projection MMA.
// min-blocks 6 -> <=42 regs -> 75% occupancy (latency-bound kernel).
// ---------------------------------------------------------------------------
__global__ void __launch_bounds__(256, 6) sample_kernel(
    const float* __restrict__ qpos,
    const int*   __restrict__ qlvl,
    const int*   __restrict__ qbo)
{
    const int tid = threadIdx.x;
    const int q0  = blockIdx.x * 4;
    const int qi  = tid >> 6;            // query slot in block (0..3)
    const int q   = q0 + qi;
    const int tq  = tid & 63;            // thread within query
    const int h   = tq >> 3;             // head (0..7)
    const int lg  = tq & 7;              // lane in head group; channels lg*4..lg*4+3

    __shared__ float s_scaled[4][NLEV][2];
    __shared__ int   s_b[4];

    if (tid < 32) {
        int qi2 = tid >> 3, idx = tid & 7;
        int l = idx >> 1, c = idx & 1;
        int qq = q0 + qi2;
        int ql = qlvl[qq];
        float shp_q = (float)(64 >> ql);
        float shp_l = (float)(64 >> l);
        s_scaled[qi2][l][c] = (qpos[qq * 2 + c] / shp_q) * shp_l;
    }
    if (tid < 4) {
        s_b[tid] = (qbo[1] <= q0 + tid) ? 1 : 0;
    }
    __syncthreads();

    const float* oa = g_offattw + q * 384;

    // softmax over 16 logits of this head: 2 logits per lane, width-8 segments
    float a0 = oa[256 + lg * 16 + h];
    float a1 = oa[256 + lg * 16 + 8 + h];
    float mx = fmaxf(a0, a1);
    #pragma unroll
    for (int j = 4; j >= 1; j >>= 1) mx = fmaxf(mx, __shfl_xor_sync(0xffffffffu, mx, j, 8));
    float e0 = __expf(a0 - mx);
    float e1 = __expf(a1 - mx);
    float s = e0 + e1;
    #pragma unroll
    for (int j = 4; j >= 1; j >>= 1) s += __shfl_xor_sync(0xffffffffu, s, j, 8);
    float inv = __frcp_rn(s);
    float w0 = e0 * inv;
    float w1 = e1 * inv;

    float2 off_a = *reinterpret_cast<const float2*>(oa + (lg * 16 + h) * 2);
    float2 off_b = *reinterpret_cast<const float2*>(oa + (lg * 16 + 8 + h) * 2);

    const int b = s_b[qi];
    const int base = (b * TOKB) * EMB + h * HD + lg * 4;
    float4 acc = {0.0f, 0.0f, 0.0f, 0.0f};
    const float4 zero = {0.0f, 0.0f, 0.0f, 0.0f};

    #pragma unroll
    for (int l = 0; l < NLEV; ++l) {
        const int   sh = 6 - l;
        const int   Wl = 64 >> l;
        const float Hf = (float)Wl;
        const float sc_h = s_scaled[qi][l][0];
        const float sc_w = s_scaled[qi][l][1];
        const float* vb = g_values + base + c_loff[l] * EMB;
        const int rowStep = Wl << 8;

        #pragma unroll
        for (int p = 0; p < NPTS; ++p) {
            const int i = p * NLEV + l;
            float offh = __shfl_sync(0xffffffffu, (i & 1) ? off_b.x : off_a.x, i >> 1, 8);
            float offw = __shfl_sync(0xffffffffu, (i & 1) ? off_b.y : off_a.y, i >> 1, 8);
            float aw   = __shfl_sync(0xffffffffu, (i & 1) ? w1     : w0,      i >> 1, 8);

            float hf = fminf(fmaxf(sc_h + offh, 0.0f), Hf);
            float wf = fminf(fmaxf(sc_w + offw, 0.0f), Hf);
            float h0f = floorf(hf), w0f = floorf(wf);
            float fh = hf - h0f,    fw = wf - w0f;
            int h0 = (int)h0f, w0i = (int)w0f;

            bool h0ok = h0 < Wl;
            bool h1ok = (h0 + 1) < Wl;
            bool w0ok = w0i < Wl;
            bool w1ok = (w0i + 1) < Wl;

            int idx = ((h0 << sh) + w0i) << 8;

            float4 v00 = (h0ok && w0ok) ? *reinterpret_cast<const float4*>(vb + idx)                 : zero;
            float4 v01 = (h0ok && w1ok) ? *reinterpret_cast<const float4*>(vb + idx + EMB)           : zero;
            float4 v10 = (h1ok && w0ok) ? *reinterpret_cast<const float4*>(vb + idx + rowStep)       : zero;
            float4 v11 = (h1ok && w1ok) ? *reinterpret_cast<const float4*>(vb + idx + rowStep + EMB) : zero;

            float4 top, bot;
            top.x = v00.x + fw * (v01.x - v00.x);
            top.y = v00.y + fw * (v01.y - v00.y);
            top.z = v00.z + fw * (v01.z - v00.z);
            top.w = v00.w + fw * (v01.w - v00.w);
            bot.x = v10.x + fw * (v11.x - v10.x);
            bot.y = v10.y + fw * (v11.y - v10.y);
            bot.z = v10.z + fw * (v11.z - v10.z);
            bot.w = v10.w + fw * (v11.w - v10.w);
            acc.x += aw * (top.x + fh * (bot.x - top.x));
            acc.y += aw * (top.y + fh * (bot.y - top.y));
            acc.z += aw * (top.z + fh * (bot.z - top.z));
            acc.w += aw * (top.w + fh * (bot.w - top.w));
        }
    }

    split_store4(acc, g_shi, g_slo, q * EMB + h * HD + lg * 4);
}

// ---------------------------------------------------------------------------
extern "C" void kernel_launch(void* const* d_in, const int* in_sizes, int n_in,
                              void* d_out, int out_size)
{
    const float* query  = (const float*)d_in[0];
    const float* qpos   = (const float*)d_in[1];
    const int*   qbo    = (const int*)  d_in[2];
    const float* fm     = (const float*)d_in[3];
    // d_in[4] = level_spatial_shapes (compile-time constants here)
    const int*   qlvl   = (const int*)  d_in[5];
    const float* W_off  = (const float*)d_in[6];
    const float* b_off  = (const float*)d_in[7];
    const float* W_attn = (const float*)d_in[8];
    const float* b_attn = (const float*)d_in[9];
    const float* W_val  = (const float*)d_in[10];
    const float* b_val  = (const float*)d_in[11];
    const float* W_out  = (const float*)d_in[12];
    const float* b_out  = (const float*)d_in[13];
    float* out = (float*)d_out;

    cudaFuncSetAttribute(mma_fused_kernel, cudaFuncAttributeMaxDynamicSharedMemorySize, SM_TOT);
    cudaFuncSetAttribute(mma_out_kernel,   cudaFuncAttributeMaxDynamicSharedMemorySize, SM_TOT);

    // 1) fp32 -> bf16 hi/lo splits (query, gathered fm rows, transposed weights)
    split_inputs_kernel<<<NQ * 64 / 256, 256>>>(query, fm);
    split_w_kernel<<<896, 256>>>(W_val, W_off, W_attn, W_out);
    // 2) tensor-core MMAs: values projection + offsets + attn logits
    mma_fused_kernel<<<dim3(NQ / 128, 5), 256, SM_TOT>>>(b_val, b_off, b_attn);
    // 3) softmax + bilinear sampling + head-weighted accumulation (writes split)
    sample_kernel<<<NQ / 4, 256>>>(qpos, qlvl, qbo);
    // 4) output projection MMA -> d_out
    mma_out_kernel<<<dim3(NQ / 128, 2), 256, SM_TOT>>>(b_out, out);
}